// round 5
// baseline (speedup 1.0000x reference)
#include <cuda_runtime.h>

#define T_STEPS 2048
#define BATCH   512
#define NH      32
#define NC      5
#define NWORD   32000

typedef unsigned long long u64;

// Precomputed input-projection table: E2[w][j] = b_rnn[j] + sum_k emb[w][k]*Wx[k][j]
__device__ float g_E2[NWORD * NH];

__device__ __forceinline__ float tanha(float x) {
    float r; asm("tanh.approx.f32 %0, %1;" : "=f"(r) : "f"(x)); return r;
}

// ============================================================================
// Kernel 1: build E2 table. One warp per word. Memory-bound, ~8 MB traffic.
// ============================================================================
__global__ void __launch_bounds__(256) build_e2(
    const float* __restrict__ emb,    // (32000, 32)
    const float* __restrict__ W_rnn,  // (64, 32): rows 0..31 = Wx
    const float* __restrict__ b_rnn)  // (32,)
{
    const int j = threadIdx.x & 31;
    const int w = blockIdx.x * (blockDim.x >> 5) + (threadIdx.x >> 5);
    if (w >= NWORD) return;

    const float4* pe = reinterpret_cast<const float4*>(emb) + (long long)w * 8;
    float4 e[8];
    #pragma unroll
    for (int m = 0; m < 8; m++) e[m] = __ldg(pe + m);

    float a0 = __ldg(b_rnn + j), a1 = 0.f, a2 = 0.f, a3 = 0.f;
    #pragma unroll
    for (int m = 0; m < 8; m++) {
        a0 = fmaf(e[m].x, __ldg(W_rnn + (4*m+0)*NH + j), a0);
        a1 = fmaf(e[m].y, __ldg(W_rnn + (4*m+1)*NH + j), a1);
        a2 = fmaf(e[m].z, __ldg(W_rnn + (4*m+2)*NH + j), a2);
        a3 = fmaf(e[m].w, __ldg(W_rnn + (4*m+3)*NH + j), a3);
    }
    g_E2[w * NH + j] = (a0 + a1) + (a2 + a3);
}

// ============================================================================
// Kernel 2: recurrence. One warp per batch row, lane j = hidden unit j.
// h broadcast via 32 immediate-lane shuffles; plain scalar FFMA matvec.
// u(t) = E2[x[t]][j] — single coalesced gather, 4-deep register pipeline.
// x indices fetched as int4 (one LDG.128 per 4 steps).
// ============================================================================
__global__ void __launch_bounds__(128, 1) rnn_rec(
    const int*   __restrict__ x,      // (T, B)
    const float* __restrict__ W_rnn,  // (64, 32): rows 32..63 = Wh
    const float* __restrict__ W_cls,  // (32, 5)
    const float* __restrict__ b_cls,  // (5,)
    float*       __restrict__ out)    // (B, 5)
{
    const int warp = threadIdx.x >> 5;
    const int j    = threadIdx.x & 31;
    const int brow = (blockIdx.x << 2) + warp;

    // Wh column j, one scalar per k
    float wh[NH];
    #pragma unroll
    for (int k = 0; k < NH; k++) wh[k] = __ldg(W_rnn + (NH + k)*NH + j);

    const float* e2j = g_E2 + j;

    // x is (T, B): x[t][brow]. Lane-cooperative int4 chunks:
    // chunk c covers t in [4c, 4c+4). Stored column-major per row, stride B.
    // We need per-warp scalar indices; all lanes read the same int4 (uniform).
    const int* xb = x + brow;

    // idx chunk pipeline: ic0 = indices for t in [t, t+4), ic1 = [t+4, t+8)
    int4 ic0, ic1;
    {
        // gather 4 strided ints -> int4 (can't LDG.128: stride is B, not 1)
        ic0.x = __ldg(xb + 0*BATCH); ic0.y = __ldg(xb + 1*BATCH);
        ic0.z = __ldg(xb + 2*BATCH); ic0.w = __ldg(xb + 3*BATCH);
        ic1.x = __ldg(xb + 4*BATCH); ic1.y = __ldg(xb + 5*BATCH);
        ic1.z = __ldg(xb + 6*BATCH); ic1.w = __ldg(xb + 7*BATCH);
    }

    // u pipeline: up[p] = u(t+p), 4 deep
    float up[4];
    up[0] = __ldg(e2j + (size_t)ic0.x * NH);
    up[1] = __ldg(e2j + (size_t)ic0.y * NH);
    up[2] = __ldg(e2j + (size_t)ic0.z * NH);
    up[3] = __ldg(e2j + (size_t)ic0.w * NH);
    ic0 = ic1;

    float h = 0.f;

    #define ONESTEP(UP_SLOT, NEXT_IDX)                                          \
    {                                                                           \
        float b0, b1, b2, b3, b4, b5, b6, b7;                                   \
        float a0 = up[UP_SLOT], a1 = 0.f, a2 = 0.f, a3 = 0.f;                   \
        float a4 = 0.f, a5 = 0.f, a6 = 0.f, a7 = 0.f;                           \
        b0 = __shfl_sync(~0u, h, 0);  b1 = __shfl_sync(~0u, h, 1);              \
        b2 = __shfl_sync(~0u, h, 2);  b3 = __shfl_sync(~0u, h, 3);              \
        b4 = __shfl_sync(~0u, h, 4);  b5 = __shfl_sync(~0u, h, 5);              \
        b6 = __shfl_sync(~0u, h, 6);  b7 = __shfl_sync(~0u, h, 7);              \
        a0 = fmaf(b0, wh[0], a0);  a1 = fmaf(b1, wh[1], a1);                    \
        a2 = fmaf(b2, wh[2], a2);  a3 = fmaf(b3, wh[3], a3);                    \
        a4 = fmaf(b4, wh[4], a4);  a5 = fmaf(b5, wh[5], a5);                    \
        a6 = fmaf(b6, wh[6], a6);  a7 = fmaf(b7, wh[7], a7);                    \
        b0 = __shfl_sync(~0u, h, 8);  b1 = __shfl_sync(~0u, h, 9);              \
        b2 = __shfl_sync(~0u, h, 10); b3 = __shfl_sync(~0u, h, 11);             \
        b4 = __shfl_sync(~0u, h, 12); b5 = __shfl_sync(~0u, h, 13);             \
        b6 = __shfl_sync(~0u, h, 14); b7 = __shfl_sync(~0u, h, 15);             \
        a0 = fmaf(b0, wh[8],  a0); a1 = fmaf(b1, wh[9],  a1);                   \
        a2 = fmaf(b2, wh[10], a2); a3 = fmaf(b3, wh[11], a3);                   \
        a4 = fmaf(b4, wh[12], a4); a5 = fmaf(b5, wh[13], a5);                   \
        a6 = fmaf(b6, wh[14], a6); a7 = fmaf(b7, wh[15], a7);                   \
        b0 = __shfl_sync(~0u, h, 16); b1 = __shfl_sync(~0u, h, 17);             \
        b2 = __shfl_sync(~0u, h, 18); b3 = __shfl_sync(~0u, h, 19);             \
        b4 = __shfl_sync(~0u, h, 20); b5 = __shfl_sync(~0u, h, 21);             \
        b6 = __shfl_sync(~0u, h, 22); b7 = __shfl_sync(~0u, h, 23);             \
        a0 = fmaf(b0, wh[16], a0); a1 = fmaf(b1, wh[17], a1);                   \
        a2 = fmaf(b2, wh[18], a2); a3 = fmaf(b3, wh[19], a3);                   \
        a4 = fmaf(b4, wh[20], a4); a5 = fmaf(b5, wh[21], a5);                   \
        a6 = fmaf(b6, wh[22], a6); a7 = fmaf(b7, wh[23], a7);                   \
        b0 = __shfl_sync(~0u, h, 24); b1 = __shfl_sync(~0u, h, 25);             \
        b2 = __shfl_sync(~0u, h, 26); b3 = __shfl_sync(~0u, h, 27);             \
        b4 = __shfl_sync(~0u, h, 28); b5 = __shfl_sync(~0u, h, 29);             \
        b6 = __shfl_sync(~0u, h, 30); b7 = __shfl_sync(~0u, h, 31);             \
        a0 = fmaf(b0, wh[24], a0); a1 = fmaf(b1, wh[25], a1);                   \
        a2 = fmaf(b2, wh[26], a2); a3 = fmaf(b3, wh[27], a3);                   \
        a4 = fmaf(b4, wh[28], a4); a5 = fmaf(b5, wh[29], a5);                   \
        a6 = fmaf(b6, wh[30], a6); a7 = fmaf(b7, wh[31], a7);                   \
        a0 += a1; a2 += a3; a4 += a5; a6 += a7;                                 \
        a0 += a2; a4 += a6;                                                     \
        h = tanha(a0 + a4);                                                     \
        up[UP_SLOT] = __ldg(e2j + (size_t)(NEXT_IDX) * NH);                     \
    }

    // main loop: 4 steps per iteration; u prefetch distance 4.
    // Iteration at time t: consumes u(t..t+3) (from ic-indices loaded earlier),
    // refills with u(t+4..t+7) using ic0 (= idx(t+4..t+7)), then loads
    // idx(t+8..t+11) into ic0 for the next iteration.
    for (int t = 0; t < T_STEPS; t += 4) {
        ONESTEP(0, ic0.x);
        ONESTEP(1, ic0.y);
        ONESTEP(2, ic0.z);
        ONESTEP(3, ic0.w);
        int tb = t + 8;
        tb = (tb <= T_STEPS - 4) ? tb : (T_STEPS - 4);
        const int* xp = xb + tb * BATCH;
        ic0.x = __ldg(xp + 0*BATCH); ic0.y = __ldg(xp + 1*BATCH);
        ic0.z = __ldg(xp + 2*BATCH); ic0.w = __ldg(xp + 3*BATCH);
    }

    // ---- epilogue: y = h_final @ W_cls + b_cls ----
    #pragma unroll
    for (int c = 0; c < NC; c++) {
        float vv = h * __ldg(W_cls + j * NC + c);
        #pragma unroll
        for (int off = 16; off; off >>= 1)
            vv += __shfl_xor_sync(0xffffffffu, vv, off);
        if (j == 0) out[brow * NC + c] = vv + __ldg(b_cls + c);
    }
}

extern "C" void kernel_launch(void* const* d_in, const int* in_sizes, int n_in,
                              void* d_out, int out_size) {
    (void)in_sizes; (void)n_in; (void)out_size;
    build_e2<<<(NWORD + 7) / 8, 256>>>(
        (const float*)d_in[1],
        (const float*)d_in[2],
        (const float*)d_in[3]);
    rnn_rec<<<BATCH / 4, 128>>>(
        (const int*)d_in[0],
        (const float*)d_in[2],
        (const float*)d_in[4],
        (const float*)d_in[5],
        (float*)d_out);
}

// round 6
// speedup vs baseline: 1.0470x; 1.0470x over previous
#include <cuda_runtime.h>
#include <cuda_fp16.h>
#include <string.h>

#define T_STEPS 2048
#define BATCH   512
#define NH      32
#define NC      5
#define NWORD   32000

// Precomputed input-projection table: E2[w][j] = b_rnn[j] + sum_k emb[w][k]*Wx[k][j]
__device__ float g_E2[NWORD * NH];

__device__ __forceinline__ float tanha(float x) {
    float r; asm("tanh.approx.f32 %0, %1;" : "=f"(r) : "f"(x)); return r;
}
__device__ __forceinline__ unsigned h2u(__half2 h) { unsigned r; memcpy(&r, &h, 4); return r; }
__device__ __forceinline__ __half2 u2h(unsigned u) { __half2 h; memcpy(&h, &u, 4); return h; }

// ============================================================================
// Kernel 1: build E2 table. One warp per word. Memory-bound, ~12 MB traffic.
// ============================================================================
__global__ void __launch_bounds__(256) build_e2(
    const float* __restrict__ emb,    // (32000, 32)
    const float* __restrict__ W_rnn,  // (64, 32): rows 0..31 = Wx
    const float* __restrict__ b_rnn)  // (32,)
{
    const int j = threadIdx.x & 31;
    const int w = blockIdx.x * (blockDim.x >> 5) + (threadIdx.x >> 5);
    if (w >= NWORD) return;

    const float4* pe = reinterpret_cast<const float4*>(emb) + (long long)w * 8;
    float4 e[8];
    #pragma unroll
    for (int m = 0; m < 8; m++) e[m] = __ldg(pe + m);

    float a0 = __ldg(b_rnn + j), a1 = 0.f, a2 = 0.f, a3 = 0.f;
    #pragma unroll
    for (int m = 0; m < 8; m++) {
        a0 = fmaf(e[m].x, __ldg(W_rnn + (4*m+0)*NH + j), a0);
        a1 = fmaf(e[m].y, __ldg(W_rnn + (4*m+1)*NH + j), a1);
        a2 = fmaf(e[m].z, __ldg(W_rnn + (4*m+2)*NH + j), a2);
        a3 = fmaf(e[m].w, __ldg(W_rnn + (4*m+3)*NH + j), a3);
    }
    g_E2[w * NH + j] = (a0 + a1) + (a2 + a3);
}

// ============================================================================
// Kernel 2: recurrence. One warp per batch row.
// Lane l: m = l&15, k-half kb = l&16. Computes outputs (2m, 2m+1) over its
// k-half only (16 k each); shfl.xor(16) combines halves.
// h broadcast as fp16x2 pairs: 8 shfl.idx + 2 shfl.xor = 10 SHFL/step.
// ============================================================================
__global__ void __launch_bounds__(128, 1) rnn_rec(
    const int*   __restrict__ x,      // (T, B)
    const float* __restrict__ W_rnn,  // (64, 32): rows 32..63 = Wh
    const float* __restrict__ W_cls,  // (32, 5)
    const float* __restrict__ b_cls,  // (5,)
    float*       __restrict__ out)    // (B, 5)
{
    __shared__ float sh[4][NH];

    const int warp = threadIdx.x >> 5;
    const int l    = threadIdx.x & 31;
    const int brow = (blockIdx.x << 2) + warp;
    const int m    = l & 15;
    const int kb   = l & 16;          // this lane's k-half base
    const int jA   = 2 * m;
    const int jB   = 2 * m + 1;

    // Wh slices: whA[kk] = Wh[kb+kk][jA], whB[kk] = Wh[kb+kk][jB]
    float whA[16], whB[16];
    #pragma unroll
    for (int kk = 0; kk < 16; kk++) {
        whA[kk] = __ldg(W_rnn + (NH + kb + kk) * NH + jA);
        whB[kk] = __ldg(W_rnn + (NH + kb + kk) * NH + jB);
    }

    // shfl source base: pairs p = kb/2 .. kb/2+7 live in lanes p and p+16.
    // lower half reads lanes 0..7, upper half reads lanes 24..31.
    const int s0 = kb + (kb >> 1);    // 0 or 24

    // E2 gather as float2: row = 16 float2, our pair at offset m.
    const float2* e2p = reinterpret_cast<const float2*>(g_E2);
    const int* xb = x + brow;

    // idx pipeline (4 per block of steps) + u pipeline (float2, distance 4)
    int4 ic0, ic1;
    ic0.x = __ldg(xb + 0*BATCH); ic0.y = __ldg(xb + 1*BATCH);
    ic0.z = __ldg(xb + 2*BATCH); ic0.w = __ldg(xb + 3*BATCH);
    ic1.x = __ldg(xb + 4*BATCH); ic1.y = __ldg(xb + 5*BATCH);
    ic1.z = __ldg(xb + 6*BATCH); ic1.w = __ldg(xb + 7*BATCH);

    float2 up2[4];
    up2[0] = __ldg(e2p + (size_t)ic0.x * 16 + m);
    up2[1] = __ldg(e2p + (size_t)ic0.y * 16 + m);
    up2[2] = __ldg(e2p + (size_t)ic0.z * 16 + m);
    up2[3] = __ldg(e2p + (size_t)ic0.w * 16 + m);
    ic0 = ic1;

    unsigned pku = 0u;   // fp16x2 (h_jA, h_jB) = (0, 0)
    float hAl = 0.f, hBl = 0.f;

    #define ONESTEP(P, NEXT_IDX)                                                \
    {                                                                           \
        unsigned q0 = __shfl_sync(~0u, pku, s0 + 0);                            \
        unsigned q1 = __shfl_sync(~0u, pku, s0 + 1);                            \
        unsigned q2 = __shfl_sync(~0u, pku, s0 + 2);                            \
        unsigned q3 = __shfl_sync(~0u, pku, s0 + 3);                            \
        unsigned q4 = __shfl_sync(~0u, pku, s0 + 4);                            \
        unsigned q5 = __shfl_sync(~0u, pku, s0 + 5);                            \
        unsigned q6 = __shfl_sync(~0u, pku, s0 + 6);                            \
        unsigned q7 = __shfl_sync(~0u, pku, s0 + 7);                            \
        float2 f0 = __half22float2(u2h(q0));                                    \
        float2 f1 = __half22float2(u2h(q1));                                    \
        float2 f2 = __half22float2(u2h(q2));                                    \
        float2 f3 = __half22float2(u2h(q3));                                    \
        float2 f4 = __half22float2(u2h(q4));                                    \
        float2 f5 = __half22float2(u2h(q5));                                    \
        float2 f6 = __half22float2(u2h(q6));                                    \
        float2 f7 = __half22float2(u2h(q7));                                    \
        float a0 = 0.f, a1 = 0.f, a2 = 0.f, a3 = 0.f;                           \
        float b0 = 0.f, b1 = 0.f, b2 = 0.f, b3 = 0.f;                           \
        a0 = fmaf(f0.x, whA[0],  a0);  b0 = fmaf(f0.x, whB[0],  b0);            \
        a1 = fmaf(f0.y, whA[1],  a1);  b1 = fmaf(f0.y, whB[1],  b1);            \
        a2 = fmaf(f1.x, whA[2],  a2);  b2 = fmaf(f1.x, whB[2],  b2);            \
        a3 = fmaf(f1.y, whA[3],  a3);  b3 = fmaf(f1.y, whB[3],  b3);            \
        a0 = fmaf(f2.x, whA[4],  a0);  b0 = fmaf(f2.x, whB[4],  b0);            \
        a1 = fmaf(f2.y, whA[5],  a1);  b1 = fmaf(f2.y, whB[5],  b1);            \
        a2 = fmaf(f3.x, whA[6],  a2);  b2 = fmaf(f3.x, whB[6],  b2);            \
        a3 = fmaf(f3.y, whA[7],  a3);  b3 = fmaf(f3.y, whB[7],  b3);            \
        a0 = fmaf(f4.x, whA[8],  a0);  b0 = fmaf(f4.x, whB[8],  b0);            \
        a1 = fmaf(f4.y, whA[9],  a1);  b1 = fmaf(f4.y, whB[9],  b1);            \
        a2 = fmaf(f5.x, whA[10], a2);  b2 = fmaf(f5.x, whB[10], b2);            \
        a3 = fmaf(f5.y, whA[11], a3);  b3 = fmaf(f5.y, whB[11], b3);            \
        a0 = fmaf(f6.x, whA[12], a0);  b0 = fmaf(f6.x, whB[12], b0);            \
        a1 = fmaf(f6.y, whA[13], a1);  b1 = fmaf(f6.y, whB[13], b1);            \
        a2 = fmaf(f7.x, whA[14], a2);  b2 = fmaf(f7.x, whB[14], b2);            \
        a3 = fmaf(f7.y, whA[15], a3);  b3 = fmaf(f7.y, whB[15], b3);            \
        float pA = (a0 + a1) + (a2 + a3);                                       \
        float pB = (b0 + b1) + (b2 + b3);                                       \
        pA += __shfl_xor_sync(~0u, pA, 16);                                     \
        pB += __shfl_xor_sync(~0u, pB, 16);                                     \
        float2 uu = up2[P];                                                     \
        float hA = tanha(pA + uu.x);                                            \
        float hB = tanha(pB + uu.y);                                            \
        pku = h2u(__floats2half2_rn(hA, hB));                                   \
        hAl = hA; hBl = hB;                                                     \
        up2[P] = __ldg(e2p + (size_t)(NEXT_IDX) * 16 + m);                      \
    }

    for (int t = 0; t < T_STEPS; t += 4) {
        ONESTEP(0, ic0.x);
        ONESTEP(1, ic0.y);
        ONESTEP(2, ic0.z);
        ONESTEP(3, ic0.w);
        int tb = t + 8;
        tb = (tb <= T_STEPS - 4) ? tb : (T_STEPS - 4);
        const int* xp = xb + tb * BATCH;
        ic0.x = __ldg(xp + 0*BATCH); ic0.y = __ldg(xp + 1*BATCH);
        ic0.z = __ldg(xp + 2*BATCH); ic0.w = __ldg(xp + 3*BATCH);
    }

    // ---- epilogue: scatter final h to smem, then y = h @ W_cls + b_cls ----
    if (l < 16) { sh[warp][jA] = hAl; sh[warp][jB] = hBl; }
    __syncwarp();
    float h = sh[warp][l];
    #pragma unroll
    for (int c = 0; c < NC; c++) {
        float vv = h * __ldg(W_cls + l * NC + c);
        #pragma unroll
        for (int off = 16; off; off >>= 1)
            vv += __shfl_xor_sync(0xffffffffu, vv, off);
        if (l == 0) out[brow * NC + c] = vv + __ldg(b_cls + c);
    }
}

extern "C" void kernel_launch(void* const* d_in, const int* in_sizes, int n_in,
                              void* d_out, int out_size) {
    (void)in_sizes; (void)n_in; (void)out_size;
    build_e2<<<(NWORD + 7) / 8, 256>>>(
        (const float*)d_in[1],
        (const float*)d_in[2],
        (const float*)d_in[3]);
    rnn_rec<<<BATCH / 4, 128>>>(
        (const int*)d_in[0],
        (const float*)d_in[2],
        (const float*)d_in[4],
        (const float*)d_in[5],
        (float*)d_out);
}

// round 7
// speedup vs baseline: 1.2227x; 1.1679x over previous
#include <cuda_runtime.h>
#include <cuda_fp16.h>
#include <string.h>

#define T_STEPS 2048
#define BATCH   512
#define NH      32
#define NC      5
#define NWORD   32000

// Precomputed input-projection table: E2[w][j] = b_rnn[j] + sum_k emb[w][k]*Wx[k][j]
__device__ float g_E2[NWORD * NH];

__device__ __forceinline__ float tanha(float x) {
    float r; asm("tanh.approx.f32 %0, %1;" : "=f"(r) : "f"(x)); return r;
}
__device__ __forceinline__ unsigned h2u(__half2 h) { unsigned r; memcpy(&r, &h, 4); return r; }
__device__ __forceinline__ __half2 u2h(unsigned u) { __half2 h; memcpy(&h, &u, 4); return h; }

// ============================================================================
// Kernel 1: build E2 table. One warp per word. Memory-bound, ~12 MB traffic.
// ============================================================================
__global__ void __launch_bounds__(256) build_e2(
    const float* __restrict__ emb,    // (32000, 32)
    const float* __restrict__ W_rnn,  // (64, 32): rows 0..31 = Wx
    const float* __restrict__ b_rnn)  // (32,)
{
    const int j = threadIdx.x & 31;
    const int w = blockIdx.x * (blockDim.x >> 5) + (threadIdx.x >> 5);
    if (w >= NWORD) return;

    const float4* pe = reinterpret_cast<const float4*>(emb) + (long long)w * 8;
    float4 e[8];
    #pragma unroll
    for (int m = 0; m < 8; m++) e[m] = __ldg(pe + m);

    float a0 = __ldg(b_rnn + j), a1 = 0.f, a2 = 0.f, a3 = 0.f;
    #pragma unroll
    for (int m = 0; m < 8; m++) {
        a0 = fmaf(e[m].x, __ldg(W_rnn + (4*m+0)*NH + j), a0);
        a1 = fmaf(e[m].y, __ldg(W_rnn + (4*m+1)*NH + j), a1);
        a2 = fmaf(e[m].z, __ldg(W_rnn + (4*m+2)*NH + j), a2);
        a3 = fmaf(e[m].w, __ldg(W_rnn + (4*m+3)*NH + j), a3);
    }
    g_E2[w * NH + j] = (a0 + a1) + (a2 + a3);
}

// ============================================================================
// Kernel 2: recurrence. TWO batch rows per warp (16 lanes each).
// Lane l: half = l>>4 selects the row; m = l&15 owns outputs jA=2m, jB=2m+1.
// Comm: h stored as fp16x2 pair per lane; 16 shfl.idx per step delivers all
// pairs to every lane of the row. Math: 32 HFMA2 per lane = 2 outputs x 32 k
// (k-pairs multiply shuffled h-pairs directly; no dup/unpack on the MAC path).
// ============================================================================
__global__ void __launch_bounds__(128, 1) rnn_rec(
    const int*   __restrict__ x,      // (T, B)
    const float* __restrict__ W_rnn,  // (64, 32): rows 32..63 = Wh
    const float* __restrict__ W_cls,  // (32, 5)
    const float* __restrict__ b_cls,  // (5,)
    float*       __restrict__ out)    // (B, 5)
{
    const int warp = threadIdx.x >> 5;
    const int l    = threadIdx.x & 31;
    const int half = l >> 4;            // which row in this warp
    const int m    = l & 15;            // pair index within the row
    const int brow = (blockIdx.x << 3) + (warp << 1) + half;
    const int jA   = 2 * m;
    const int jB   = 2 * m + 1;
    const int base = half << 4;         // shfl source base for this row

    // Wh columns jA/jB as k-paired half2: wh2A[p] = (Wh[2p][jA], Wh[2p+1][jA])
    __half2 wh2A[16], wh2B[16];
    #pragma unroll
    for (int p = 0; p < 16; p++) {
        wh2A[p] = __floats2half2_rn(__ldg(W_rnn + (NH + 2*p)     * NH + jA),
                                    __ldg(W_rnn + (NH + 2*p + 1) * NH + jA));
        wh2B[p] = __floats2half2_rn(__ldg(W_rnn + (NH + 2*p)     * NH + jB),
                                    __ldg(W_rnn + (NH + 2*p + 1) * NH + jB));
    }

    // E2 gather as float2: row = 16 float2, this lane's pair at offset m.
    const float2* e2p = reinterpret_cast<const float2*>(g_E2);
    const int* xb = x + brow;

    // idx pipeline + u pipeline (distance 4)
    int4 ic0, ic1;
    ic0.x = __ldg(xb + 0*BATCH); ic0.y = __ldg(xb + 1*BATCH);
    ic0.z = __ldg(xb + 2*BATCH); ic0.w = __ldg(xb + 3*BATCH);
    ic1.x = __ldg(xb + 4*BATCH); ic1.y = __ldg(xb + 5*BATCH);
    ic1.z = __ldg(xb + 6*BATCH); ic1.w = __ldg(xb + 7*BATCH);

    float2 up2[4];
    up2[0] = __ldg(e2p + (size_t)ic0.x * 16 + m);
    up2[1] = __ldg(e2p + (size_t)ic0.y * 16 + m);
    up2[2] = __ldg(e2p + (size_t)ic0.z * 16 + m);
    up2[3] = __ldg(e2p + (size_t)ic0.w * 16 + m);
    ic0 = ic1;

    unsigned pku = 0u;                  // fp16x2 (h_jA, h_jB) = (0,0)
    float hAl = 0.f, hBl = 0.f;
    const __half2 z2 = __floats2half2_rn(0.f, 0.f);

    #define ONESTEP(P, NEXT_IDX)                                                \
    {                                                                           \
        __half2 q0  = u2h(__shfl_sync(~0u, pku, base + 0));                     \
        __half2 q1  = u2h(__shfl_sync(~0u, pku, base + 1));                     \
        __half2 q2  = u2h(__shfl_sync(~0u, pku, base + 2));                     \
        __half2 q3  = u2h(__shfl_sync(~0u, pku, base + 3));                     \
        __half2 q4  = u2h(__shfl_sync(~0u, pku, base + 4));                     \
        __half2 q5  = u2h(__shfl_sync(~0u, pku, base + 5));                     \
        __half2 q6  = u2h(__shfl_sync(~0u, pku, base + 6));                     \
        __half2 q7  = u2h(__shfl_sync(~0u, pku, base + 7));                     \
        __half2 q8  = u2h(__shfl_sync(~0u, pku, base + 8));                     \
        __half2 q9  = u2h(__shfl_sync(~0u, pku, base + 9));                     \
        __half2 q10 = u2h(__shfl_sync(~0u, pku, base + 10));                    \
        __half2 q11 = u2h(__shfl_sync(~0u, pku, base + 11));                    \
        __half2 q12 = u2h(__shfl_sync(~0u, pku, base + 12));                    \
        __half2 q13 = u2h(__shfl_sync(~0u, pku, base + 13));                    \
        __half2 q14 = u2h(__shfl_sync(~0u, pku, base + 14));                    \
        __half2 q15 = u2h(__shfl_sync(~0u, pku, base + 15));                    \
        __half2 aA0 = z2, aA1 = z2, aA2 = z2, aA3 = z2;                         \
        __half2 aB0 = z2, aB1 = z2, aB2 = z2, aB3 = z2;                         \
        aA0 = __hfma2(q0,  wh2A[0],  aA0);  aB0 = __hfma2(q0,  wh2B[0],  aB0);  \
        aA1 = __hfma2(q1,  wh2A[1],  aA1);  aB1 = __hfma2(q1,  wh2B[1],  aB1);  \
        aA2 = __hfma2(q2,  wh2A[2],  aA2);  aB2 = __hfma2(q2,  wh2B[2],  aB2);  \
        aA3 = __hfma2(q3,  wh2A[3],  aA3);  aB3 = __hfma2(q3,  wh2B[3],  aB3);  \
        aA0 = __hfma2(q4,  wh2A[4],  aA0);  aB0 = __hfma2(q4,  wh2B[4],  aB0);  \
        aA1 = __hfma2(q5,  wh2A[5],  aA1);  aB1 = __hfma2(q5,  wh2B[5],  aB1);  \
        aA2 = __hfma2(q6,  wh2A[6],  aA2);  aB2 = __hfma2(q6,  wh2B[6],  aB2);  \
        aA3 = __hfma2(q7,  wh2A[7],  aA3);  aB3 = __hfma2(q7,  wh2B[7],  aB3);  \
        aA0 = __hfma2(q8,  wh2A[8],  aA0);  aB0 = __hfma2(q8,  wh2B[8],  aB0);  \
        aA1 = __hfma2(q9,  wh2A[9],  aA1);  aB1 = __hfma2(q9,  wh2B[9],  aB1);  \
        aA2 = __hfma2(q10, wh2A[10], aA2);  aB2 = __hfma2(q10, wh2B[10], aB2);  \
        aA3 = __hfma2(q11, wh2A[11], aA3);  aB3 = __hfma2(q11, wh2B[11], aB3);  \
        aA0 = __hfma2(q12, wh2A[12], aA0);  aB0 = __hfma2(q12, wh2B[12], aB0);  \
        aA1 = __hfma2(q13, wh2A[13], aA1);  aB1 = __hfma2(q13, wh2B[13], aB1);  \
        aA2 = __hfma2(q14, wh2A[14], aA2);  aB2 = __hfma2(q14, wh2B[14], aB2);  \
        aA3 = __hfma2(q15, wh2A[15], aA3);  aB3 = __hfma2(q15, wh2B[15], aB3);  \
        __half2 sA = __hadd2(__hadd2(aA0, aA1), __hadd2(aA2, aA3));             \
        __half2 sB = __hadd2(__hadd2(aB0, aB1), __hadd2(aB2, aB3));             \
        float2 fA = __half22float2(sA);                                         \
        float2 fB = __half22float2(sB);                                         \
        float2 uu = up2[P];                                                     \
        float hA = tanha((fA.x + fA.y) + uu.x);                                 \
        float hB = tanha((fB.x + fB.y) + uu.y);                                 \
        pku = h2u(__floats2half2_rn(hA, hB));                                   \
        hAl = hA; hBl = hB;                                                     \
        up2[P] = __ldg(e2p + (size_t)(NEXT_IDX) * 16 + m);                      \
    }

    for (int t = 0; t < T_STEPS; t += 4) {
        ONESTEP(0, ic0.x);
        ONESTEP(1, ic0.y);
        ONESTEP(2, ic0.z);
        ONESTEP(3, ic0.w);
        int tb = t + 8;
        tb = (tb <= T_STEPS - 4) ? tb : (T_STEPS - 4);
        const int* xp = xb + tb * BATCH;
        ic0.x = __ldg(xp + 0*BATCH); ic0.y = __ldg(xp + 1*BATCH);
        ic0.z = __ldg(xp + 2*BATCH); ic0.w = __ldg(xp + 3*BATCH);
    }

    // ---- epilogue: per half-warp classifier. Lane m holds (h_2m, h_2m+1). ----
    #pragma unroll
    for (int c = 0; c < NC; c++) {
        float vv = hAl * __ldg(W_cls + jA * NC + c)
                 + hBl * __ldg(W_cls + jB * NC + c);
        #pragma unroll
        for (int off = 8; off; off >>= 1)            // reduce within 16 lanes
            vv += __shfl_xor_sync(0xffffffffu, vv, off);
        if (m == 0) out[brow * NC + c] = vv + __ldg(b_cls + c);
    }
}

extern "C" void kernel_launch(void* const* d_in, const int* in_sizes, int n_in,
                              void* d_out, int out_size) {
    (void)in_sizes; (void)n_in; (void)out_size;
    build_e2<<<(NWORD + 7) / 8, 256>>>(
        (const float*)d_in[1],
        (const float*)d_in[2],
        (const float*)d_in[3]);
    rnn_rec<<<BATCH / 8, 128>>>(
        (const int*)d_in[0],
        (const float*)d_in[2],
        (const float*)d_in[4],
        (const float*)d_in[5],
        (float*)d_out);
}

// round 8
// speedup vs baseline: 1.2351x; 1.0101x over previous
#include <cuda_runtime.h>
#include <cuda_fp16.h>
#include <string.h>

#define T_STEPS 2048
#define BATCH   512
#define NH      32
#define NC      5
#define NWORD   32000

// Precomputed input-projection table: E2[w][j] = b_rnn[j] + sum_k emb[w][k]*Wx[k][j]
__device__ float g_E2[NWORD * NH];

__device__ __forceinline__ unsigned h2u(__half2 h) { unsigned r; memcpy(&r, &h, 4); return r; }
__device__ __forceinline__ __half2 u2h(unsigned u) { __half2 h; memcpy(&h, &u, 4); return h; }
__device__ __forceinline__ unsigned tanh_h2(unsigned z) {
    unsigned r; asm("tanh.approx.f16x2 %0, %1;" : "=r"(r) : "r"(z)); return r;
}
__device__ __forceinline__ unsigned hadd2u(unsigned a, unsigned b) {
    return h2u(__hadd2(u2h(a), u2h(b)));
}

// ============================================================================
// Kernel 1: build E2 table. One warp per word. Memory-bound, ~12 MB traffic.
// ============================================================================
__global__ void __launch_bounds__(256) build_e2(
    const float* __restrict__ emb,    // (32000, 32)
    const float* __restrict__ W_rnn,  // (64, 32): rows 0..31 = Wx
    const float* __restrict__ b_rnn)  // (32,)
{
    const int j = threadIdx.x & 31;
    const int w = blockIdx.x * (blockDim.x >> 5) + (threadIdx.x >> 5);
    if (w >= NWORD) return;

    const float4* pe = reinterpret_cast<const float4*>(emb) + (long long)w * 8;
    float4 e[8];
    #pragma unroll
    for (int m = 0; m < 8; m++) e[m] = __ldg(pe + m);

    float a0 = __ldg(b_rnn + j), a1 = 0.f, a2 = 0.f, a3 = 0.f;
    #pragma unroll
    for (int m = 0; m < 8; m++) {
        a0 = fmaf(e[m].x, __ldg(W_rnn + (4*m+0)*NH + j), a0);
        a1 = fmaf(e[m].y, __ldg(W_rnn + (4*m+1)*NH + j), a1);
        a2 = fmaf(e[m].z, __ldg(W_rnn + (4*m+2)*NH + j), a2);
        a3 = fmaf(e[m].w, __ldg(W_rnn + (4*m+3)*NH + j), a3);
    }
    g_E2[w * NH + j] = (a0 + a1) + (a2 + a3);
}

// ============================================================================
// Kernel 2: recurrence. TWO rows per warp, 16 lanes per row.
// Lane (p = m&7, kh = m>>3): computes outputs {2p, 2p+1, 2p+16, 2p+17} over
// k-half [16kh, 16kh+16). 8 dist shfl.idx + 1 reduce shfl.xor = 9 SHFL/step.
// After reduce, lane m holds the full pre-activation pair m; tanh.approx.f16x2
// produces the packed h-pair directly (no cvt/pack on the chain).
// ============================================================================
__global__ void __launch_bounds__(128, 1) rnn_rec(
    const int*   __restrict__ x,      // (T, B)
    const float* __restrict__ W_rnn,  // (64, 32): rows 32..63 = Wh
    const float* __restrict__ W_cls,  // (32, 5)
    const float* __restrict__ b_cls,  // (5,)
    float*       __restrict__ out)    // (B, 5)
{
    const int warp = threadIdx.x >> 5;
    const int l    = threadIdx.x & 31;
    const int row  = l >> 4;            // row within warp
    const int m    = l & 15;            // pair index this lane will own
    const int p    = m & 7;
    const int kh   = m >> 3;            // k-half: k in [16kh, 16kh+16)
    const int brow = (blockIdx.x << 3) + (warp << 1) + row;
    const int base = row << 4;
    const int s0   = base + (kh << 3);  // dist sources: s0 .. s0+7

    // Outputs: j0=2p, j1=2p+1 (pair p), j2=2p+16, j3=2p+17 (pair p+8).
    // wX[i] = (Wh[16kh+2i][jX], Wh[16kh+2i+1][jX]) for k-pair i of our k-half.
    __half2 wA[8], wB[8], wC[8], wD[8];
    #pragma unroll
    for (int i = 0; i < 8; i++) {
        const int k0 = NH + 16*kh + 2*i;      // row in W_rnn (Wh block)
        const int k1 = k0 + 1;
        wA[i] = __floats2half2_rn(__ldg(W_rnn + k0*NH + 2*p),      __ldg(W_rnn + k1*NH + 2*p));
        wB[i] = __floats2half2_rn(__ldg(W_rnn + k0*NH + 2*p + 1),  __ldg(W_rnn + k1*NH + 2*p + 1));
        wC[i] = __floats2half2_rn(__ldg(W_rnn + k0*NH + 2*p + 16), __ldg(W_rnn + k1*NH + 2*p + 16));
        wD[i] = __floats2half2_rn(__ldg(W_rnn + k0*NH + 2*p + 17), __ldg(W_rnn + k1*NH + 2*p + 17));
    }

    // E2 gather: lane owns pair m -> float2 at row offset m, pre-cvt to half2.
    const float2* e2p = reinterpret_cast<const float2*>(g_E2);
    const int* xb = x + brow;

    int4 ic0, ic1;
    ic0.x = __ldg(xb + 0*BATCH); ic0.y = __ldg(xb + 1*BATCH);
    ic0.z = __ldg(xb + 2*BATCH); ic0.w = __ldg(xb + 3*BATCH);
    ic1.x = __ldg(xb + 4*BATCH); ic1.y = __ldg(xb + 5*BATCH);
    ic1.z = __ldg(xb + 6*BATCH); ic1.w = __ldg(xb + 7*BATCH);

    unsigned uph[4];
    {
        float2 u0 = __ldg(e2p + (size_t)ic0.x * 16 + m);
        float2 u1 = __ldg(e2p + (size_t)ic0.y * 16 + m);
        float2 u2 = __ldg(e2p + (size_t)ic0.z * 16 + m);
        float2 u3 = __ldg(e2p + (size_t)ic0.w * 16 + m);
        uph[0] = h2u(__floats2half2_rn(u0.x, u0.y));
        uph[1] = h2u(__floats2half2_rn(u1.x, u1.y));
        uph[2] = h2u(__floats2half2_rn(u2.x, u2.y));
        uph[3] = h2u(__floats2half2_rn(u3.x, u3.y));
    }
    ic0 = ic1;

    unsigned pku = 0u;                  // packed (h_{2m}, h_{2m+1}) = (0,0)
    const __half2 z2 = __floats2half2_rn(0.f, 0.f);

    #define ONESTEP(P, NEXT_IDX)                                                \
    {                                                                           \
        __half2 q0 = u2h(__shfl_sync(~0u, pku, s0 + 0));                        \
        __half2 q1 = u2h(__shfl_sync(~0u, pku, s0 + 1));                        \
        __half2 q2 = u2h(__shfl_sync(~0u, pku, s0 + 2));                        \
        __half2 q3 = u2h(__shfl_sync(~0u, pku, s0 + 3));                        \
        __half2 q4 = u2h(__shfl_sync(~0u, pku, s0 + 4));                        \
        __half2 q5 = u2h(__shfl_sync(~0u, pku, s0 + 5));                        \
        __half2 q6 = u2h(__shfl_sync(~0u, pku, s0 + 6));                        \
        __half2 q7 = u2h(__shfl_sync(~0u, pku, s0 + 7));                        \
        __half2 aA0 = z2, aA1 = z2, aB0 = z2, aB1 = z2;                         \
        __half2 aC0 = z2, aC1 = z2, aD0 = z2, aD1 = z2;                         \
        aA0 = __hfma2(q0, wA[0], aA0);  aA1 = __hfma2(q1, wA[1], aA1);          \
        aB0 = __hfma2(q0, wB[0], aB0);  aB1 = __hfma2(q1, wB[1], aB1);          \
        aC0 = __hfma2(q0, wC[0], aC0);  aC1 = __hfma2(q1, wC[1], aC1);          \
        aD0 = __hfma2(q0, wD[0], aD0);  aD1 = __hfma2(q1, wD[1], aD1);          \
        aA0 = __hfma2(q2, wA[2], aA0);  aA1 = __hfma2(q3, wA[3], aA1);          \
        aB0 = __hfma2(q2, wB[2], aB0);  aB1 = __hfma2(q3, wB[3], aB1);          \
        aC0 = __hfma2(q2, wC[2], aC0);  aC1 = __hfma2(q3, wC[3], aC1);          \
        aD0 = __hfma2(q2, wD[2], aD0);  aD1 = __hfma2(q3, wD[3], aD1);          \
        aA0 = __hfma2(q4, wA[4], aA0);  aA1 = __hfma2(q5, wA[5], aA1);          \
        aB0 = __hfma2(q4, wB[4], aB0);  aB1 = __hfma2(q5, wB[5], aB1);          \
        aC0 = __hfma2(q4, wC[4], aC0);  aC1 = __hfma2(q5, wC[5], aC1);          \
        aD0 = __hfma2(q4, wD[4], aD0);  aD1 = __hfma2(q5, wD[5], aD1);          \
        aA0 = __hfma2(q6, wA[6], aA0);  aA1 = __hfma2(q7, wA[7], aA1);          \
        aB0 = __hfma2(q6, wB[6], aB0);  aB1 = __hfma2(q7, wB[7], aB1);          \
        aC0 = __hfma2(q6, wC[6], aC0);  aC1 = __hfma2(q7, wC[7], aC1);          \
        aD0 = __hfma2(q6, wD[6], aD0);  aD1 = __hfma2(q7, wD[7], aD1);          \
        unsigned PA = h2u(__hadd2(aA0, aA1));                                   \
        unsigned PB = h2u(__hadd2(aB0, aB1));                                   \
        unsigned PC = h2u(__hadd2(aC0, aC1));                                   \
        unsigned PD = h2u(__hadd2(aD0, aD1));                                   \
        /* pair-major pack: pairP = (A_e+A_o, B_e+B_o), pairQ = (C.., D..) */   \
        unsigned pP = hadd2u(__byte_perm(PA, PB, 0x5410),                       \
                             __byte_perm(PA, PB, 0x7632));                      \
        unsigned pQ = hadd2u(__byte_perm(PC, PD, 0x5410),                       \
                             __byte_perm(PC, PD, 0x7632));                      \
        /* lane keeps pair (p + 8*kh): kh==0 -> pP, kh==1 -> pQ */              \
        unsigned snd = kh ? pP : pQ;                                            \
        unsigned kp  = kh ? pQ : pP;                                            \
        unsigned rcv = __shfl_xor_sync(~0u, snd, 8);                            \
        unsigned zf  = hadd2u(hadd2u(kp, rcv), uph[P]);                         \
        pku = tanh_h2(zf);                                                      \
        float2 uu = __ldg(e2p + (size_t)(NEXT_IDX) * 16 + m);                   \
        uph[P] = h2u(__floats2half2_rn(uu.x, uu.y));                            \
    }

    for (int t = 0; t < T_STEPS; t += 4) {
        ONESTEP(0, ic0.x);
        ONESTEP(1, ic0.y);
        ONESTEP(2, ic0.z);
        ONESTEP(3, ic0.w);
        int tb = t + 8;
        tb = (tb <= T_STEPS - 4) ? tb : (T_STEPS - 4);
        const int* xp = xb + tb * BATCH;
        ic0.x = __ldg(xp + 0*BATCH); ic0.y = __ldg(xp + 1*BATCH);
        ic0.z = __ldg(xp + 2*BATCH); ic0.w = __ldg(xp + 3*BATCH);
    }

    // ---- epilogue: lane m holds final h-pair m (packed fp16x2). ----
    float2 hf = __half22float2(u2h(pku));
    #pragma unroll
    for (int c = 0; c < NC; c++) {
        float vv = hf.x * __ldg(W_cls + (2*m)   * NC + c)
                 + hf.y * __ldg(W_cls + (2*m+1) * NC + c);
        #pragma unroll
        for (int off = 8; off; off >>= 1)     // reduce across the row's 16 lanes
            vv += __shfl_xor_sync(0xffffffffu, vv, off);
        if (m == 0) out[brow * NC + c] = vv + __ldg(b_cls + c);
    }
}

extern "C" void kernel_launch(void* const* d_in, const int* in_sizes, int n_in,
                              void* d_out, int out_size) {
    (void)in_sizes; (void)n_in; (void)out_size;
    build_e2<<<(NWORD + 7) / 8, 256>>>(
        (const float*)d_in[1],
        (const float*)d_in[2],
        (const float*)d_in[3]);
    rnn_rec<<<BATCH / 8, 128>>>(
        (const int*)d_in[0],
        (const float*)d_in[2],
        (const float*)d_in[4],
        (const float*)d_in[5],
        (float*)d_out);
}

// round 9
// speedup vs baseline: 1.2785x; 1.0351x over previous
#include <cuda_runtime.h>
#include <cuda_fp16.h>
#include <string.h>

#define T_STEPS 2048
#define BATCH   512
#define NH      32
#define NC      5
#define NWORD   32000

// Precomputed input-projection table: E2[w][j] = b_rnn[j] + sum_k emb[w][k]*Wx[k][j]
__device__ float g_E2[NWORD * NH];

__device__ __forceinline__ unsigned h2u(__half2 h) { unsigned r; memcpy(&r, &h, 4); return r; }
__device__ __forceinline__ __half2 u2h(unsigned u) { __half2 h; memcpy(&h, &u, 4); return h; }
__device__ __forceinline__ unsigned tanh_h2(unsigned z) {
    unsigned r; asm("tanh.approx.f16x2 %0, %1;" : "=r"(r) : "r"(z)); return r;
}
__device__ __forceinline__ unsigned hadd2u(unsigned a, unsigned b) {
    return h2u(__hadd2(u2h(a), u2h(b)));
}

// ============================================================================
// Kernel 1: build E2 table. One warp per word. Memory-bound, ~12 MB traffic.
// ============================================================================
__global__ void __launch_bounds__(256) build_e2(
    const float* __restrict__ emb,    // (32000, 32)
    const float* __restrict__ W_rnn,  // (64, 32): rows 0..31 = Wx
    const float* __restrict__ b_rnn)  // (32,)
{
    const int j = threadIdx.x & 31;
    const int w = blockIdx.x * (blockDim.x >> 5) + (threadIdx.x >> 5);
    if (w >= NWORD) return;

    const float4* pe = reinterpret_cast<const float4*>(emb) + (long long)w * 8;
    float4 e[8];
    #pragma unroll
    for (int m = 0; m < 8; m++) e[m] = __ldg(pe + m);

    float a0 = __ldg(b_rnn + j), a1 = 0.f, a2 = 0.f, a3 = 0.f;
    #pragma unroll
    for (int m = 0; m < 8; m++) {
        a0 = fmaf(e[m].x, __ldg(W_rnn + (4*m+0)*NH + j), a0);
        a1 = fmaf(e[m].y, __ldg(W_rnn + (4*m+1)*NH + j), a1);
        a2 = fmaf(e[m].z, __ldg(W_rnn + (4*m+2)*NH + j), a2);
        a3 = fmaf(e[m].w, __ldg(W_rnn + (4*m+3)*NH + j), a3);
    }
    g_E2[w * NH + j] = (a0 + a1) + (a2 + a3);
}

// ============================================================================
// Kernel 2: recurrence. TWO rows per warp, 16 lanes per row.
// Structure identical to round-8 (9 SHFL/step, HFMA2 matvec, fp16x2 tanh),
// EXCEPT: 8-step unroll with u-gather distance 8 and idx prefetch distance
// 8-16 steps, so no LDG latency is ever exposed at iteration boundaries.
// ============================================================================
__global__ void __launch_bounds__(128, 1) rnn_rec(
    const int*   __restrict__ x,      // (T, B)
    const float* __restrict__ W_rnn,  // (64, 32): rows 32..63 = Wh
    const float* __restrict__ W_cls,  // (32, 5)
    const float* __restrict__ b_cls,  // (5,)
    float*       __restrict__ out)    // (B, 5)
{
    const int warp = threadIdx.x >> 5;
    const int l    = threadIdx.x & 31;
    const int row  = l >> 4;            // row within warp
    const int m    = l & 15;            // pair index this lane will own
    const int p    = m & 7;
    const int kh   = m >> 3;            // k-half: k in [16kh, 16kh+16)
    const int brow = (blockIdx.x << 3) + (warp << 1) + row;
    const int base = row << 4;
    const int s0   = base + (kh << 3);  // dist sources: s0 .. s0+7

    // Outputs: j0=2p, j1=2p+1 (pair p), j2=2p+16, j3=2p+17 (pair p+8).
    __half2 wA[8], wB[8], wC[8], wD[8];
    #pragma unroll
    for (int i = 0; i < 8; i++) {
        const int k0 = NH + 16*kh + 2*i;
        const int k1 = k0 + 1;
        wA[i] = __floats2half2_rn(__ldg(W_rnn + k0*NH + 2*p),      __ldg(W_rnn + k1*NH + 2*p));
        wB[i] = __floats2half2_rn(__ldg(W_rnn + k0*NH + 2*p + 1),  __ldg(W_rnn + k1*NH + 2*p + 1));
        wC[i] = __floats2half2_rn(__ldg(W_rnn + k0*NH + 2*p + 16), __ldg(W_rnn + k1*NH + 2*p + 16));
        wD[i] = __floats2half2_rn(__ldg(W_rnn + k0*NH + 2*p + 17), __ldg(W_rnn + k1*NH + 2*p + 17));
    }

    const float2* e2p = reinterpret_cast<const float2*>(g_E2);
    const int* xb = x + brow;

    // ---- prime pipelines ----
    // idxq[P] always holds idx(t+8+P) when step t+P runs (distance 8..16).
    int idxq[8];
    #pragma unroll
    for (int P = 0; P < 8; P++) idxq[P] = __ldg(xb + (8 + P) * BATCH);

    // uph[P] holds u(t+P) as half2 (distance-8 gather).
    unsigned uph[8];
    #pragma unroll
    for (int P = 0; P < 8; P++) {
        int id = __ldg(xb + P * BATCH);
        float2 uu = __ldg(e2p + (size_t)id * 16 + m);
        uph[P] = h2u(__floats2half2_rn(uu.x, uu.y));
    }

    unsigned pku = 0u;                  // packed (h_{2m}, h_{2m+1}) = (0,0)
    const __half2 z2 = __floats2half2_rn(0.f, 0.f);

    #define ONESTEP(P)                                                          \
    {                                                                           \
        __half2 q0 = u2h(__shfl_sync(~0u, pku, s0 + 0));                        \
        __half2 q1 = u2h(__shfl_sync(~0u, pku, s0 + 1));                        \
        __half2 q2 = u2h(__shfl_sync(~0u, pku, s0 + 2));                        \
        __half2 q3 = u2h(__shfl_sync(~0u, pku, s0 + 3));                        \
        __half2 q4 = u2h(__shfl_sync(~0u, pku, s0 + 4));                        \
        __half2 q5 = u2h(__shfl_sync(~0u, pku, s0 + 5));                        \
        __half2 q6 = u2h(__shfl_sync(~0u, pku, s0 + 6));                        \
        __half2 q7 = u2h(__shfl_sync(~0u, pku, s0 + 7));                        \
        __half2 aA0 = z2, aA1 = z2, aB0 = z2, aB1 = z2;                         \
        __half2 aC0 = z2, aC1 = z2, aD0 = z2, aD1 = z2;                         \
        aA0 = __hfma2(q0, wA[0], aA0);  aA1 = __hfma2(q1, wA[1], aA1);          \
        aB0 = __hfma2(q0, wB[0], aB0);  aB1 = __hfma2(q1, wB[1], aB1);          \
        aC0 = __hfma2(q0, wC[0], aC0);  aC1 = __hfma2(q1, wC[1], aC1);          \
        aD0 = __hfma2(q0, wD[0], aD0);  aD1 = __hfma2(q1, wD[1], aD1);          \
        aA0 = __hfma2(q2, wA[2], aA0);  aA1 = __hfma2(q3, wA[3], aA1);          \
        aB0 = __hfma2(q2, wB[2], aB0);  aB1 = __hfma2(q3, wB[3], aB1);          \
        aC0 = __hfma2(q2, wC[2], aC0);  aC1 = __hfma2(q3, wC[3], aC1);          \
        aD0 = __hfma2(q2, wD[2], aD0);  aD1 = __hfma2(q3, wD[3], aD1);          \
        aA0 = __hfma2(q4, wA[4], aA0);  aA1 = __hfma2(q5, wA[5], aA1);          \
        aB0 = __hfma2(q4, wB[4], aB0);  aB1 = __hfma2(q5, wB[5], aB1);          \
        aC0 = __hfma2(q4, wC[4], aC0);  aC1 = __hfma2(q5, wC[5], aC1);          \
        aD0 = __hfma2(q4, wD[4], aD0);  aD1 = __hfma2(q5, wD[5], aD1);          \
        aA0 = __hfma2(q6, wA[6], aA0);  aA1 = __hfma2(q7, wA[7], aA1);          \
        aB0 = __hfma2(q6, wB[6], aB0);  aB1 = __hfma2(q7, wB[7], aB1);          \
        aC0 = __hfma2(q6, wC[6], aC0);  aC1 = __hfma2(q7, wC[7], aC1);          \
        aD0 = __hfma2(q6, wD[6], aD0);  aD1 = __hfma2(q7, wD[7], aD1);          \
        unsigned PA = h2u(__hadd2(aA0, aA1));                                   \
        unsigned PB = h2u(__hadd2(aB0, aB1));                                   \
        unsigned PC = h2u(__hadd2(aC0, aC1));                                   \
        unsigned PD = h2u(__hadd2(aD0, aD1));                                   \
        unsigned pP = hadd2u(__byte_perm(PA, PB, 0x5410),                       \
                             __byte_perm(PA, PB, 0x7632));                      \
        unsigned pQ = hadd2u(__byte_perm(PC, PD, 0x5410),                       \
                             __byte_perm(PC, PD, 0x7632));                      \
        unsigned snd = kh ? pP : pQ;                                            \
        unsigned kp  = kh ? pQ : pP;                                            \
        unsigned rcv = __shfl_xor_sync(~0u, snd, 8);                            \
        unsigned zf  = hadd2u(hadd2u(kp, rcv), uph[P]);                         \
        pku = tanh_h2(zf);                                                      \
        /* refill: u(t+P+8) via idxq[P] (loaded >= 8 steps ago) */              \
        float2 uu = __ldg(e2p + (size_t)idxq[P] * 16 + m);                      \
        uph[P] = h2u(__floats2half2_rn(uu.x, uu.y));                            \
    }

    for (int t = 0; t < T_STEPS; t += 8) {
        ONESTEP(0);
        ONESTEP(1);
        ONESTEP(2);
        ONESTEP(3);
        ONESTEP(4);
        ONESTEP(5);
        ONESTEP(6);
        ONESTEP(7);
        // load idx(t+16 .. t+23); first consumer is next iteration's
        // ONESTEP(0) refill — 8..16 steps from now.
        int tb = t + 16;
        tb = (tb <= T_STEPS - 8) ? tb : (T_STEPS - 8);
        const int* xp = xb + tb * BATCH;
        #pragma unroll
        for (int P = 0; P < 8; P++) idxq[P] = __ldg(xp + P * BATCH);
    }

    // ---- epilogue: lane m holds final h-pair m (packed fp16x2). ----
    float2 hf = __half22float2(u2h(pku));
    #pragma unroll
    for (int c = 0; c < NC; c++) {
        float vv = hf.x * __ldg(W_cls + (2*m)   * NC + c)
                 + hf.y * __ldg(W_cls + (2*m+1) * NC + c);
        #pragma unroll
        for (int off = 8; off; off >>= 1)     // reduce across the row's 16 lanes
            vv += __shfl_xor_sync(0xffffffffu, vv, off);
        if (m == 0) out[brow * NC + c] = vv + __ldg(b_cls + c);
    }
}

extern "C" void kernel_launch(void* const* d_in, const int* in_sizes, int n_in,
                              void* d_out, int out_size) {
    (void)in_sizes; (void)n_in; (void)out_size;
    build_e2<<<(NWORD + 7) / 8, 256>>>(
        (const float*)d_in[1],
        (const float*)d_in[2],
        (const float*)d_in[3]);
    rnn_rec<<<BATCH / 8, 128>>>(
        (const int*)d_in[0],
        (const float*)d_in[2],
        (const float*)d_in[4],
        (const float*)d_in[5],
        (float*)d_out);
}

// round 10
// speedup vs baseline: 1.5347x; 1.2004x over previous
#include <cuda_runtime.h>
#include <cuda_fp16.h>
#include <string.h>

#define T_STEPS 2048
#define BATCH   512
#define NH      32
#define NC      5
#define NWORD   32000

// Precomputed input-projection table: E2[w][j] = b_rnn[j] + sum_k emb[w][k]*Wx[k][j]
__device__ float g_E2[NWORD * NH];

__device__ __forceinline__ unsigned h2u(__half2 h) { unsigned r; memcpy(&r, &h, 4); return r; }
__device__ __forceinline__ __half2 u2h(unsigned u) { __half2 h; memcpy(&h, &u, 4); return h; }
__device__ __forceinline__ unsigned tanh_h2(unsigned z) {
    unsigned r; asm("tanh.approx.f16x2 %0, %1;" : "=r"(r) : "r"(z)); return r;
}
__device__ __forceinline__ unsigned hadd2u(unsigned a, unsigned b) {
    return h2u(__hadd2(u2h(a), u2h(b)));
}

// ============================================================================
// Kernel 1: build E2 table. One warp per word. Memory-bound, ~12 MB traffic.
// ============================================================================
__global__ void __launch_bounds__(256) build_e2(
    const float* __restrict__ emb,    // (32000, 32)
    const float* __restrict__ W_rnn,  // (64, 32): rows 0..31 = Wx
    const float* __restrict__ b_rnn)  // (32,)
{
    const int j = threadIdx.x & 31;
    const int w = blockIdx.x * (blockDim.x >> 5) + (threadIdx.x >> 5);
    if (w >= NWORD) return;

    const float4* pe = reinterpret_cast<const float4*>(emb) + (long long)w * 8;
    float4 e[8];
    #pragma unroll
    for (int m = 0; m < 8; m++) e[m] = __ldg(pe + m);

    float a0 = __ldg(b_rnn + j), a1 = 0.f, a2 = 0.f, a3 = 0.f;
    #pragma unroll
    for (int m = 0; m < 8; m++) {
        a0 = fmaf(e[m].x, __ldg(W_rnn + (4*m+0)*NH + j), a0);
        a1 = fmaf(e[m].y, __ldg(W_rnn + (4*m+1)*NH + j), a1);
        a2 = fmaf(e[m].z, __ldg(W_rnn + (4*m+2)*NH + j), a2);
        a3 = fmaf(e[m].w, __ldg(W_rnn + (4*m+3)*NH + j), a3);
    }
    g_E2[w * NH + j] = (a0 + a1) + (a2 + a3);
}

// ============================================================================
// Kernel 2: recurrence. ONE row per warp, 32 lanes.
// Lane l: m = l&15 owns output pair (2m, 2m+1); kh = l>>4 is its k-half.
// Lanes m and m+16 both hold pair m after tanh (replicated), so distribution
// sources are lanes 8kh..8kh+7 (kh=0 copies). Per step: 8 dist shfl + 1
// symmetric xor-16 reduce shfl = 9 SHFL serving ONE row (halved per-row work
// vs 2-rows/warp); 16 HFMA2; u added before the reduce (off post-shfl chain).
// ============================================================================
__global__ void __launch_bounds__(128, 1) rnn_rec(
    const int*   __restrict__ x,      // (T, B)
    const float* __restrict__ W_rnn,  // (64, 32): rows 32..63 = Wh
    const float* __restrict__ W_cls,  // (32, 5)
    const float* __restrict__ b_cls,  // (5,)
    float*       __restrict__ out)    // (B, 5)
{
    const int warp = threadIdx.x >> 5;
    const int l    = threadIdx.x & 31;
    const int m    = l & 15;            // output pair owned
    const int kh   = l >> 4;            // k-half: k in [16kh, 16kh+16)
    const int brow = (blockIdx.x << 2) + warp;
    const int s0   = kh << 3;           // dist sources: lanes s0 .. s0+7

    // Outputs jA=2m, jB=2m+1 over k-half [16kh, 16kh+16):
    // wX[i] = (Wh[16kh+2i][jX], Wh[16kh+2i+1][jX])
    __half2 wA[8], wB[8];
    #pragma unroll
    for (int i = 0; i < 8; i++) {
        const int k0 = NH + 16*kh + 2*i;
        const int k1 = k0 + 1;
        wA[i] = __floats2half2_rn(__ldg(W_rnn + k0*NH + 2*m),     __ldg(W_rnn + k1*NH + 2*m));
        wB[i] = __floats2half2_rn(__ldg(W_rnn + k0*NH + 2*m + 1), __ldg(W_rnn + k1*NH + 2*m + 1));
    }

    const float2* e2p = reinterpret_cast<const float2*>(g_E2);
    const int* xb = x + brow;

    // ---- prime pipelines (same scheme as round 9) ----
    int idxq[8];
    #pragma unroll
    for (int P = 0; P < 8; P++) idxq[P] = __ldg(xb + (8 + P) * BATCH);

    unsigned uph[8];
    #pragma unroll
    for (int P = 0; P < 8; P++) {
        int id = __ldg(xb + P * BATCH);
        float2 uu = __ldg(e2p + (size_t)id * 16 + m);
        uph[P] = h2u(__floats2half2_rn(uu.x, uu.y));
    }

    unsigned pku = 0u;                  // packed (h_{2m}, h_{2m+1}) = (0,0)
    const __half2 z2 = __floats2half2_rn(0.f, 0.f);

    #define ONESTEP(P)                                                          \
    {                                                                           \
        __half2 q0 = u2h(__shfl_sync(~0u, pku, s0 + 0));                        \
        __half2 q1 = u2h(__shfl_sync(~0u, pku, s0 + 1));                        \
        __half2 q2 = u2h(__shfl_sync(~0u, pku, s0 + 2));                        \
        __half2 q3 = u2h(__shfl_sync(~0u, pku, s0 + 3));                        \
        __half2 q4 = u2h(__shfl_sync(~0u, pku, s0 + 4));                        \
        __half2 q5 = u2h(__shfl_sync(~0u, pku, s0 + 5));                        \
        __half2 q6 = u2h(__shfl_sync(~0u, pku, s0 + 6));                        \
        __half2 q7 = u2h(__shfl_sync(~0u, pku, s0 + 7));                        \
        __half2 aA0 = z2, aA1 = z2, aB0 = z2, aB1 = z2;                         \
        aA0 = __hfma2(q0, wA[0], aA0);  aA1 = __hfma2(q1, wA[1], aA1);          \
        aB0 = __hfma2(q0, wB[0], aB0);  aB1 = __hfma2(q1, wB[1], aB1);          \
        aA0 = __hfma2(q2, wA[2], aA0);  aA1 = __hfma2(q3, wA[3], aA1);          \
        aB0 = __hfma2(q2, wB[2], aB0);  aB1 = __hfma2(q3, wB[3], aB1);          \
        aA0 = __hfma2(q4, wA[4], aA0);  aA1 = __hfma2(q5, wA[5], aA1);          \
        aB0 = __hfma2(q4, wB[4], aB0);  aB1 = __hfma2(q5, wB[5], aB1);          \
        aA0 = __hfma2(q6, wA[6], aA0);  aA1 = __hfma2(q7, wA[7], aA1);          \
        aB0 = __hfma2(q6, wB[6], aB0);  aB1 = __hfma2(q7, wB[7], aB1);          \
        unsigned PA = h2u(__hadd2(aA0, aA1));                                   \
        unsigned PB = h2u(__hadd2(aB0, aB1));                                   \
        /* pack pair-partial: (A_lo+A_hi, B_lo+B_hi) */                         \
        unsigned zk = hadd2u(__byte_perm(PA, PB, 0x5410),                       \
                             __byte_perm(PA, PB, 0x7632));                      \
        /* add u BEFORE the reduce (kh=0 side carries it; kh=1 adds zero) */    \
        zk = hadd2u(zk, kh ? 0u : uph[P]);                                      \
        unsigned rcv = __shfl_xor_sync(~0u, zk, 16);                            \
        pku = tanh_h2(hadd2u(zk, rcv));                                         \
        /* refill: u(t+P+8) via idxq[P] (loaded >= 8 steps ago) */              \
        float2 uu = __ldg(e2p + (size_t)idxq[P] * 16 + m);                      \
        uph[P] = h2u(__floats2half2_rn(uu.x, uu.y));                            \
    }

    for (int t = 0; t < T_STEPS; t += 8) {
        ONESTEP(0);
        ONESTEP(1);
        ONESTEP(2);
        ONESTEP(3);
        ONESTEP(4);
        ONESTEP(5);
        ONESTEP(6);
        ONESTEP(7);
        int tb = t + 16;
        tb = (tb <= T_STEPS - 8) ? tb : (T_STEPS - 8);
        const int* xp = xb + tb * BATCH;
        #pragma unroll
        for (int P = 0; P < 8; P++) idxq[P] = __ldg(xp + P * BATCH);
    }

    // ---- epilogue: lane m (and m+16) holds final h-pair m. ----
    float2 hf = __half22float2(u2h(pku));
    #pragma unroll
    for (int c = 0; c < NC; c++) {
        float vv = hf.x * __ldg(W_cls + (2*m)   * NC + c)
                 + hf.y * __ldg(W_cls + (2*m+1) * NC + c);
        #pragma unroll
        for (int off = 8; off; off >>= 1)     // reduce across 16 pair-owners
            vv += __shfl_xor_sync(0xffffffffu, vv, off);
        if (l == 0) out[brow * NC + c] = vv + __ldg(b_cls + c);
    }
}

extern "C" void kernel_launch(void* const* d_in, const int* in_sizes, int n_in,
                              void* d_out, int out_size) {
    (void)in_sizes; (void)n_in; (void)out_size;
    build_e2<<<(NWORD + 7) / 8, 256>>>(
        (const float*)d_in[1],
        (const float*)d_in[2],
        (const float*)d_in[3]);
    rnn_rec<<<BATCH / 4, 128>>>(
        (const int*)d_in[0],
        (const float*)d_in[2],
        (const float*)d_in[4],
        (const float*)d_in[5],
        (float*)d_out);
}